// round 1
// baseline (speedup 1.0000x reference)
#include <cuda_runtime.h>
#include <math.h>

#define NB 8192
#define NC 100
#define NK 64
#define BT 128
#define KC 32
#define NT (NB/BT)     // 64 tiles per dim
#define LDP 132        // padded shared stride (floats): 132*4B = 528B = 33*16B -> float4-aligned rows

// Fixed-slot partial sums (deterministic reduction, no atomics)
__device__ float g_pair_partial[NT*NT];
__device__ float g_ce_yi[NB/8];
__device__ float g_ce_ym[NB/8];
__device__ float g_qua[NB/8];
__device__ float g_sq[NB];

__device__ __forceinline__ float warp_sum(float v) {
#pragma unroll
    for (int o = 16; o; o >>= 1) v += __shfl_xor_sync(0xffffffffu, v, o);
    return v;
}

// ---------------------------------------------------------------------------
// Per-row kernel over Fi: squared norms (for pairwise D) + BCE quantization sum
// warp per row; 8 warps/block; grid = NB/8 = 1024
// ---------------------------------------------------------------------------
__global__ void row_kernel(const float* __restrict__ Fi) {
    int lane = threadIdx.x & 31;
    int wib  = threadIdx.x >> 5;
    int row  = blockIdx.x * 8 + wib;
    const float* r = Fi + (size_t)row * NK;
    float p0 = r[lane];
    float p1 = r[lane + 32];
    float sq = p0 * p0 + p1 * p1;
    float q =
        -(p0 * fmaxf(logf(p0), -100.f) + (1.f - p0) * fmaxf(log1pf(-p0), -100.f))
        -(p1 * fmaxf(logf(p1), -100.f) + (1.f - p1) * fmaxf(log1pf(-p1), -100.f));
    sq = warp_sum(sq);
    q  = warp_sum(q);
    if (lane == 0) g_sq[row] = sq;

    __shared__ float s[8];
    if (lane == 0) s[wib] = q;
    __syncthreads();
    if (threadIdx.x == 0) {
        float t = 0.f;
#pragma unroll
        for (int i = 0; i < 8; i++) t += s[i];
        g_qua[blockIdx.x] = t;
    }
}

// ---------------------------------------------------------------------------
// Cross-entropy for Yi and Ym (100 classes). warp per row, both tensors.
// ---------------------------------------------------------------------------
__device__ __forceinline__ float ce_row(const float* __restrict__ x, int lane, int lbl) {
    float v[4];
    float m = -1e30f;
#pragma unroll
    for (int i = 0; i < 4; i++) {
        int c = lane + 32 * i;
        v[i] = (c < NC) ? x[c] : -1e30f;
        m = fmaxf(m, v[i]);
    }
#pragma unroll
    for (int o = 16; o; o >>= 1) m = fmaxf(m, __shfl_xor_sync(0xffffffffu, m, o));
    float s = 0.f;
#pragma unroll
    for (int i = 0; i < 4; i++) s += expf(v[i] - m);   // exp(-huge) -> 0 for padding
    s = warp_sum(s);
    return m + logf(s) - x[lbl];
}

__global__ void ce_kernel(const float* __restrict__ Yi, const float* __restrict__ Ym,
                          const int* __restrict__ yl) {
    int lane = threadIdx.x & 31;
    int wib  = threadIdx.x >> 5;
    int row  = blockIdx.x * 8 + wib;
    int lbl  = yl[row];
    float a = ce_row(Yi + (size_t)row * NC, lane, lbl);
    float b = ce_row(Ym + (size_t)row * NC, lane, lbl);

    __shared__ float s1[8], s2[8];
    if (lane == 0) { s1[wib] = a; s2[wib] = b; }
    __syncthreads();
    if (threadIdx.x == 0) {
        float t1 = 0.f, t2 = 0.f;
#pragma unroll
        for (int i = 0; i < 8; i++) { t1 += s1[i]; t2 += s2[i]; }
        g_ce_yi[blockIdx.x] = t1;
        g_ce_ym[blockIdx.x] = t2;
    }
}

// ---------------------------------------------------------------------------
// Pairwise tile kernel: 128x128 output tile / block, 8x8 per thread, K=64 in
// two 32-wide staged chunks. Upper-triangular tiles only; off-diagonal x2.
// ---------------------------------------------------------------------------
__global__ __launch_bounds__(256) void pair_kernel(const float* __restrict__ Fi,
                                                   const int* __restrict__ yl) {
    const int tj = blockIdx.x, ti = blockIdx.y;
    const int pidx = ti * NT + tj;
    if (tj < ti) {                       // lower triangle: write 0 (deterministic slots)
        if (threadIdx.x == 0) g_pair_partial[pidx] = 0.f;
        return;
    }

    __shared__ __align__(16) float As[KC][LDP];  // [k][i]
    __shared__ __align__(16) float Bs[KC][LDP];  // [k][j]
    __shared__ float sqA[BT], sqB[BT];
    __shared__ int   yA[BT],  yB[BT];
    __shared__ float red[256];

    const int tid = threadIdx.x;
    const int tx = tid & 15, ty = tid >> 4;
    const int i0 = ti * BT, j0 = tj * BT;

    if (tid < BT) { sqA[tid] = g_sq[i0 + tid]; yA[tid] = yl[i0 + tid]; }
    else          { int t = tid - BT; sqB[t] = g_sq[j0 + t]; yB[t] = yl[j0 + t]; }

    float acc[8][8];
#pragma unroll
    for (int m = 0; m < 8; m++)
#pragma unroll
        for (int n = 0; n < 8; n++) acc[m][n] = 0.f;

    for (int kc = 0; kc < NK; kc += KC) {
        // stage chunk: 128 rows x 32 k-floats each tile, transposed into [k][row]
#pragma unroll
        for (int l = 0; l < 4; l++) {
            int q   = l * 256 + tid;
            int row = q >> 3;
            int kv  = q & 7;
            float4 va = *(const float4*)(Fi + (size_t)(i0 + row) * NK + kc + kv * 4);
            As[kv*4+0][row] = va.x; As[kv*4+1][row] = va.y;
            As[kv*4+2][row] = va.z; As[kv*4+3][row] = va.w;
            float4 vb = *(const float4*)(Fi + (size_t)(j0 + row) * NK + kc + kv * 4);
            Bs[kv*4+0][row] = vb.x; Bs[kv*4+1][row] = vb.y;
            Bs[kv*4+2][row] = vb.z; Bs[kv*4+3][row] = vb.w;
        }
        __syncthreads();

#pragma unroll
        for (int k = 0; k < KC; k++) {
            float4 t0 = *(const float4*)&As[k][ty * 8];
            float4 t1 = *(const float4*)&As[k][ty * 8 + 4];
            float4 u0 = *(const float4*)&Bs[k][tx * 8];
            float4 u1 = *(const float4*)&Bs[k][tx * 8 + 4];
            float a[8] = {t0.x, t0.y, t0.z, t0.w, t1.x, t1.y, t1.z, t1.w};
            float b[8] = {u0.x, u0.y, u0.z, u0.w, u1.x, u1.y, u1.z, u1.w};
#pragma unroll
            for (int m = 0; m < 8; m++)
#pragma unroll
                for (int n = 0; n < 8; n++)
                    acc[m][n] = fmaf(a[m], b[n], acc[m][n]);
        }
        __syncthreads();
    }

    // epilogue: D -> pair -> local sum
    float local = 0.f;
#pragma unroll
    for (int m = 0; m < 8; m++) {
        float si  = sqA[ty * 8 + m];
        int   yi_ = yA[ty * 8 + m];
#pragma unroll
        for (int n = 0; n < 8; n++) {
            float D = si + sqB[tx * 8 + n] - 2.f * acc[m][n];
            D = fmaxf(D, 0.f);
            float p = (yi_ == yB[tx * 8 + n]) ? D : fmaxf(32.f - D, 0.f);
            local += p;
        }
    }
    if (ti != tj) local *= 2.f;   // account for the mirrored tile

    red[tid] = local;
    __syncthreads();
#pragma unroll
    for (int s = 128; s; s >>= 1) {
        if (tid < s) red[tid] += red[tid + s];
        __syncthreads();
    }
    if (tid == 0) g_pair_partial[pidx] = red[0];
}

// ---------------------------------------------------------------------------
// Deterministic final reduction + combine
// ---------------------------------------------------------------------------
__global__ void finalize_kernel(float* __restrict__ out) {
    __shared__ float red[256];
    int tid = threadIdx.x;
    float sp = 0.f, s1 = 0.f, s2 = 0.f, sq = 0.f;
    for (int i = tid; i < NT * NT; i += 256) sp += g_pair_partial[i];
    for (int i = tid; i < NB / 8; i += 256) {
        s1 += g_ce_yi[i]; s2 += g_ce_ym[i]; sq += g_qua[i];
    }
    float vals[4] = {sp, s1, s2, sq};
    float tot[4];
#pragma unroll
    for (int v = 0; v < 4; v++) {
        red[tid] = vals[v];
        __syncthreads();
        for (int s = 128; s; s >>= 1) {
            if (tid < s) red[tid] += red[tid + s];
            __syncthreads();
        }
        tot[v] = red[0];
        __syncthreads();
    }
    if (tid == 0) {
        // full-matrix sum S; sum_{i<j} = S/2; l_pair = (S/2) / (2*B*(B-1))
        double l_pair = (double)tot[0] / (4.0 * (double)NB * (double)(NB - 1));
        double l_sem  = (double)tot[1] / (double)NB;          // LAMTA = 1
        double l_att  = (double)tot[2] / (double)NB;          // ROU = 1
        double l_qua  = 0.1 * (double)tot[3] / ((double)NB * (double)NK);
        out[0] = (float)(l_pair + l_sem + l_att + l_qua);
    }
}

extern "C" void kernel_launch(void* const* d_in, const int* in_sizes, int n_in,
                              void* d_out, int out_size) {
    (void)in_sizes; (void)n_in; (void)out_size;
    const float* Ym = (const float*)d_in[0];
    const float* Fi = (const float*)d_in[1];
    const float* Yi = (const float*)d_in[2];
    const int*   y  = (const int*)d_in[3];
    float* out = (float*)d_out;

    row_kernel<<<NB / 8, 256>>>(Fi);
    ce_kernel<<<NB / 8, 256>>>(Yi, Ym, y);
    pair_kernel<<<dim3(NT, NT), 256>>>(Fi, y);
    finalize_kernel<<<1, 256>>>(out);
}

// round 2
// speedup vs baseline: 1.0902x; 1.0902x over previous
#include <cuda_runtime.h>
#include <math.h>

#define NB 8192
#define NC 100
#define NK 64
#define BT 128
#define KC 32
#define NT (NB/BT)                 // 64 tiles per dim
#define NPAIR (NT*(NT+1)/2)        // 2080 upper-tri tiles
#define LDP 132                    // padded shared stride (floats) -> float4/u64x2 aligned rows

// Fixed-slot partial sums (deterministic reduction, no atomics)
__device__ float g_pair_partial[NPAIR];
__device__ float g_ce_yi[NB/8];
__device__ float g_ce_ym[NB/8];
__device__ float g_qua[NB/8];
__device__ float g_sq[NB];

#define FMA2(d, a, b, c) \
    asm("fma.rn.f32x2 %0, %1, %2, %3;" : "=l"(d) : "l"(a), "l"(b), "l"(c))
#define PACK2DUP(d, x) \
    asm("mov.b64 %0, {%1, %1};" : "=l"(d) : "r"(__float_as_uint(x)))

__device__ __forceinline__ float warp_sum(float v) {
#pragma unroll
    for (int o = 16; o; o >>= 1) v += __shfl_xor_sync(0xffffffffu, v, o);
    return v;
}
__device__ __forceinline__ double warp_sum_d(double v) {
#pragma unroll
    for (int o = 16; o; o >>= 1) v += __shfl_xor_sync(0xffffffffu, v, o);
    return v;
}

// ---------------------------------------------------------------------------
// Fused prep: blocks [0,1024) -> Fi row norms + BCE quantization
//             blocks [1024,2048) -> cross-entropy for Yi and Ym
// ---------------------------------------------------------------------------
__device__ __forceinline__ float ce_row(const float* __restrict__ x, int lane, int lbl) {
    float v[4];
    float m = -1e30f;
#pragma unroll
    for (int i = 0; i < 4; i++) {
        int c = lane + 32 * i;
        v[i] = (c < NC) ? x[c] : -1e30f;
        m = fmaxf(m, v[i]);
    }
#pragma unroll
    for (int o = 16; o; o >>= 1) m = fmaxf(m, __shfl_xor_sync(0xffffffffu, m, o));
    float s = 0.f;
#pragma unroll
    for (int i = 0; i < 4; i++) s += expf(v[i] - m);
    s = warp_sum(s);
    return m + logf(s) - x[lbl];
}

__global__ void prep_kernel(const float* __restrict__ Fi,
                            const float* __restrict__ Yi,
                            const float* __restrict__ Ym,
                            const int* __restrict__ yl) {
    int lane = threadIdx.x & 31;
    int wib  = threadIdx.x >> 5;
    __shared__ float s1[8], s2[8];

    if (blockIdx.x < NB / 8) {
        // row norms + quantization
        int row = blockIdx.x * 8 + wib;
        const float* r = Fi + (size_t)row * NK;
        float p0 = r[lane];
        float p1 = r[lane + 32];
        float sq = p0 * p0 + p1 * p1;
        float q =
            -(p0 * fmaxf(logf(p0), -100.f) + (1.f - p0) * fmaxf(log1pf(-p0), -100.f))
            -(p1 * fmaxf(logf(p1), -100.f) + (1.f - p1) * fmaxf(log1pf(-p1), -100.f));
        sq = warp_sum(sq);
        q  = warp_sum(q);
        if (lane == 0) { g_sq[row] = sq; s1[wib] = q; }
        __syncthreads();
        if (threadIdx.x == 0) {
            float t = 0.f;
#pragma unroll
            for (int i = 0; i < 8; i++) t += s1[i];
            g_qua[blockIdx.x] = t;
        }
    } else {
        int blk = blockIdx.x - NB / 8;
        int row = blk * 8 + wib;
        int lbl = yl[row];
        float a = ce_row(Yi + (size_t)row * NC, lane, lbl);
        float b = ce_row(Ym + (size_t)row * NC, lane, lbl);
        if (lane == 0) { s1[wib] = a; s2[wib] = b; }
        __syncthreads();
        if (threadIdx.x == 0) {
            float t1 = 0.f, t2 = 0.f;
#pragma unroll
            for (int i = 0; i < 8; i++) { t1 += s1[i]; t2 += s2[i]; }
            g_ce_yi[blk] = t1;
            g_ce_ym[blk] = t2;
        }
    }
}

// ---------------------------------------------------------------------------
// Pairwise tile kernel (FFMA2): 128x128 tile per block, 8x8 per thread as
// 8x4 f32x2 accumulators. 1-D triangular launch (upper tiles only).
// ---------------------------------------------------------------------------
__global__ __launch_bounds__(256, 2) void pair_kernel(const float* __restrict__ Fi,
                                                      const int* __restrict__ yl) {
    // decode linear upper-tri tile index -> (ti, tj), tj >= ti
    int idx = blockIdx.x;
    int ti = (int)((2.f * NT + 1.f - sqrtf((2.f * NT + 1.f) * (2.f * NT + 1.f) - 8.f * (float)idx)) * 0.5f);
    while (ti > 0 && ti * NT - ti * (ti - 1) / 2 > idx) ti--;
    while ((ti + 1) * NT - (ti + 1) * ti / 2 <= idx) ti++;
    int tj = ti + (idx - (ti * NT - ti * (ti - 1) / 2));

    __shared__ __align__(16) float As[KC][LDP];  // [k][i]
    __shared__ __align__(16) float Bs[KC][LDP];  // [k][j]
    __shared__ float sqA[BT], sqB[BT];
    __shared__ int   yA[BT],  yB[BT];
    __shared__ float red[8];

    const int tid = threadIdx.x;
    const int tx = tid & 15, ty = tid >> 4;
    const int i0 = ti * BT, j0 = tj * BT;

    if (tid < BT) { sqA[tid] = g_sq[i0 + tid]; yA[tid] = yl[i0 + tid]; }
    else          { int t = tid - BT; sqB[t] = g_sq[j0 + t]; yB[t] = yl[j0 + t]; }

    unsigned long long acc2[8][4];
#pragma unroll
    for (int m = 0; m < 8; m++)
#pragma unroll
        for (int n = 0; n < 4; n++) acc2[m][n] = 0ULL;

    for (int kc = 0; kc < NK; kc += KC) {
        // stage chunk: 128 rows x 32 k-floats per tile, transposed into [k][row]
#pragma unroll
        for (int l = 0; l < 4; l++) {
            int q   = l * 256 + tid;
            int row = q >> 3;
            int kv  = q & 7;
            float4 va = *(const float4*)(Fi + (size_t)(i0 + row) * NK + kc + kv * 4);
            As[kv*4+0][row] = va.x; As[kv*4+1][row] = va.y;
            As[kv*4+2][row] = va.z; As[kv*4+3][row] = va.w;
            float4 vb = *(const float4*)(Fi + (size_t)(j0 + row) * NK + kc + kv * 4);
            Bs[kv*4+0][row] = vb.x; Bs[kv*4+1][row] = vb.y;
            Bs[kv*4+2][row] = vb.z; Bs[kv*4+3][row] = vb.w;
        }
        __syncthreads();

#pragma unroll
        for (int k = 0; k < KC; k++) {
            float4 t0 = *(const float4*)&As[k][ty * 8];
            float4 t1 = *(const float4*)&As[k][ty * 8 + 4];
            ulonglong2 bb0 = *(const ulonglong2*)&Bs[k][tx * 8];
            ulonglong2 bb1 = *(const ulonglong2*)&Bs[k][tx * 8 + 4];
            unsigned long long b2[4] = {bb0.x, bb0.y, bb1.x, bb1.y};
            float a[8] = {t0.x, t0.y, t0.z, t0.w, t1.x, t1.y, t1.z, t1.w};
#pragma unroll
            for (int m = 0; m < 8; m++) {
                unsigned long long a2;
                PACK2DUP(a2, a[m]);
#pragma unroll
                for (int n = 0; n < 4; n++)
                    FMA2(acc2[m][n], a2, b2[n], acc2[m][n]);
            }
        }
        __syncthreads();
    }

    // epilogue: D -> pair -> local sum
    float local = 0.f;
#pragma unroll
    for (int m = 0; m < 8; m++) {
        float si  = sqA[ty * 8 + m];
        int   yi_ = yA[ty * 8 + m];
#pragma unroll
        for (int n = 0; n < 4; n++) {
            unsigned long long v = acc2[m][n];
            float clo = __uint_as_float((unsigned)(v & 0xffffffffULL));
            float chi = __uint_as_float((unsigned)(v >> 32));
            int jn0 = tx * 8 + 2 * n;
            {
                float D = si + sqB[jn0] - 2.f * clo;
                D = fmaxf(D, 0.f);
                local += (yi_ == yB[jn0]) ? D : fmaxf(32.f - D, 0.f);
            }
            {
                float D = si + sqB[jn0 + 1] - 2.f * chi;
                D = fmaxf(D, 0.f);
                local += (yi_ == yB[jn0 + 1]) ? D : fmaxf(32.f - D, 0.f);
            }
        }
    }
    if (ti != tj) local *= 2.f;   // mirrored tile

    local = warp_sum(local);
    if ((tid & 31) == 0) red[tid >> 5] = local;
    __syncthreads();
    if (tid == 0) {
        float t = 0.f;
#pragma unroll
        for (int i = 0; i < 8; i++) t += red[i];
        g_pair_partial[blockIdx.x] = t;
    }
}

// ---------------------------------------------------------------------------
// Deterministic final reduction + combine (single pass, weighted in double)
// ---------------------------------------------------------------------------
__global__ void finalize_kernel(float* __restrict__ out) {
    __shared__ double red[16];
    int tid = threadIdx.x;

    float sp = 0.f, s1 = 0.f, s2 = 0.f, sq = 0.f;
    for (int i = tid; i < NPAIR; i += 512) sp += g_pair_partial[i];
    for (int i = tid; i < NB / 8; i += 512) {
        s1 += g_ce_yi[i]; s2 += g_ce_ym[i]; sq += g_qua[i];
    }
    // weights: l_pair = S/(4*B*(B-1)); l_sem+l_att = (s1+s2)/B; l_qua = 0.1*sq/(B*K)
    double d = (double)sp * (1.0 / (4.0 * (double)NB * (double)(NB - 1)))
             + ((double)s1 + (double)s2) * (1.0 / (double)NB)
             + (double)sq * (0.1 / ((double)NB * (double)NK));
    d = warp_sum_d(d);
    if ((tid & 31) == 0) red[tid >> 5] = d;
    __syncthreads();
    if (tid == 0) {
        double t = 0.0;
#pragma unroll
        for (int i = 0; i < 16; i++) t += red[i];
        out[0] = (float)t;
    }
}

extern "C" void kernel_launch(void* const* d_in, const int* in_sizes, int n_in,
                              void* d_out, int out_size) {
    (void)in_sizes; (void)n_in; (void)out_size;
    const float* Ym = (const float*)d_in[0];
    const float* Fi = (const float*)d_in[1];
    const float* Yi = (const float*)d_in[2];
    const int*   y  = (const int*)d_in[3];
    float* out = (float*)d_out;

    prep_kernel<<<2 * (NB / 8), 256>>>(Fi, Yi, Ym, y);
    pair_kernel<<<NPAIR, 256>>>(Fi, y);
    finalize_kernel<<<1, 512>>>(out);
}

// round 4
// speedup vs baseline: 2.1322x; 1.9558x over previous
#include <cuda_runtime.h>
#include <cuda_bf16.h>
#include <math.h>
#include <stdint.h>

#define NB 8192
#define NC 100
#define NK 64
#define BT 128
#define NT (NB/BT)                 // 64 tiles per dim
#define NPAIR (NT*(NT+1)/2)        // 2080 upper-tri tiles
#define LDB 144                    // smem row stride in bytes (64 bf16 + 8 pad)
#define TILE_BYTES (BT*LDB)        // 18432
#define SM_A_HI 0
#define SM_A_LO (1*TILE_BYTES)
#define SM_B_HI (2*TILE_BYTES)
#define SM_B_LO (3*TILE_BYTES)
#define SM_DYN  (4*TILE_BYTES)     // 73728 bytes

// Fixed-slot partial sums (deterministic, no atomics)
__device__ float g_pair_partial[NPAIR];
__device__ float g_ce_yi[NB/8];
__device__ float g_ce_ym[NB/8];
__device__ float g_qua[NB/8];
__device__ float g_sq[NB];
// bf16 hi/lo split of Fi (row-major [NB][NK])
__device__ __nv_bfloat16 g_fhi[NB*NK];
__device__ __nv_bfloat16 g_flo[NB*NK];

__device__ __forceinline__ uint32_t smem_u32(const void* p) {
    uint32_t a;
    asm("{ .reg .u64 t; cvta.to.shared.u64 t, %1; cvt.u32.u64 %0, t; }" : "=r"(a) : "l"(p));
    return a;
}
__device__ __forceinline__ void ldsm_x4(uint32_t (&r)[4], uint32_t addr) {
    asm volatile("ldmatrix.sync.aligned.m8n8.x4.shared.b16 {%0,%1,%2,%3}, [%4];"
                 : "=r"(r[0]), "=r"(r[1]), "=r"(r[2]), "=r"(r[3]) : "r"(addr));
}
__device__ __forceinline__ void ldsm_x2(uint32_t (&r)[2], uint32_t addr) {
    asm volatile("ldmatrix.sync.aligned.m8n8.x2.shared.b16 {%0,%1}, [%2];"
                 : "=r"(r[0]), "=r"(r[1]) : "r"(addr));
}
__device__ __forceinline__ void mma_bf16(float (&c)[4], const uint32_t (&a)[4],
                                         const uint32_t (&b)[2]) {
    asm volatile(
        "mma.sync.aligned.m16n8k16.row.col.f32.bf16.bf16.f32 "
        "{%0,%1,%2,%3}, {%4,%5,%6,%7}, {%8,%9}, {%0,%1,%2,%3};"
        : "+f"(c[0]), "+f"(c[1]), "+f"(c[2]), "+f"(c[3])
        : "r"(a[0]), "r"(a[1]), "r"(a[2]), "r"(a[3]), "r"(b[0]), "r"(b[1]));
}

__device__ __forceinline__ float warp_sum(float v) {
#pragma unroll
    for (int o = 16; o; o >>= 1) v += __shfl_xor_sync(0xffffffffu, v, o);
    return v;
}
__device__ __forceinline__ double warp_sum_d(double v) {
#pragma unroll
    for (int o = 16; o; o >>= 1) v += __shfl_xor_sync(0xffffffffu, v, o);
    return v;
}

// ---------------------------------------------------------------------------
// Fused prep:
//  blocks [0,1024):     Fi row norms + BCE quantization
//  blocks [1024,2048):  cross-entropy for Yi and Ym
//  blocks [2048,3072):  bf16 hi/lo split of Fi
// ---------------------------------------------------------------------------
__device__ __forceinline__ float ce_row(const float* __restrict__ x, int lane, int lbl) {
    float v[4];
    float m = -1e30f;
#pragma unroll
    for (int i = 0; i < 4; i++) {
        int c = lane + 32 * i;
        v[i] = (c < NC) ? x[c] : -1e30f;
        m = fmaxf(m, v[i]);
    }
#pragma unroll
    for (int o = 16; o; o >>= 1) m = fmaxf(m, __shfl_xor_sync(0xffffffffu, m, o));
    float s = 0.f;
#pragma unroll
    for (int i = 0; i < 4; i++) s += expf(v[i] - m);
    s = warp_sum(s);
    return m + logf(s) - x[lbl];
}

__global__ void prep_kernel(const float* __restrict__ Fi,
                            const float* __restrict__ Yi,
                            const float* __restrict__ Ym,
                            const int* __restrict__ yl) {
    int lane = threadIdx.x & 31;
    int wib  = threadIdx.x >> 5;
    __shared__ float s1[8], s2[8];

    if (blockIdx.x < NB / 8) {
        int row = blockIdx.x * 8 + wib;
        const float* r = Fi + (size_t)row * NK;
        float p0 = r[lane];
        float p1 = r[lane + 32];
        float sq = p0 * p0 + p1 * p1;
        float q =
            -(p0 * fmaxf(logf(p0), -100.f) + (1.f - p0) * fmaxf(log1pf(-p0), -100.f))
            -(p1 * fmaxf(logf(p1), -100.f) + (1.f - p1) * fmaxf(log1pf(-p1), -100.f));
        sq = warp_sum(sq);
        q  = warp_sum(q);
        if (lane == 0) { g_sq[row] = sq; s1[wib] = q; }
        __syncthreads();
        if (threadIdx.x == 0) {
            float t = 0.f;
#pragma unroll
            for (int i = 0; i < 8; i++) t += s1[i];
            g_qua[blockIdx.x] = t;
        }
    } else if (blockIdx.x < 2 * (NB / 8)) {
        int blk = blockIdx.x - NB / 8;
        int row = blk * 8 + wib;
        int lbl = yl[row];
        float a = ce_row(Yi + (size_t)row * NC, lane, lbl);
        float b = ce_row(Ym + (size_t)row * NC, lane, lbl);
        if (lane == 0) { s1[wib] = a; s2[wib] = b; }
        __syncthreads();
        if (threadIdx.x == 0) {
            float t1 = 0.f, t2 = 0.f;
#pragma unroll
            for (int i = 0; i < 8; i++) { t1 += s1[i]; t2 += s2[i]; }
            g_ce_yi[blk] = t1;
            g_ce_ym[blk] = t2;
        }
    } else {
        int blk = blockIdx.x - 2 * (NB / 8);
        int base = blk * 512 + threadIdx.x * 2;
        float2 v = *(const float2*)(Fi + base);
        __nv_bfloat16 h0 = __float2bfloat16(v.x);
        __nv_bfloat16 h1 = __float2bfloat16(v.y);
        __nv_bfloat16 l0 = __float2bfloat16(v.x - __bfloat162float(h0));
        __nv_bfloat16 l1 = __float2bfloat16(v.y - __bfloat162float(h1));
        *(__nv_bfloat162*)(g_fhi + base) = __nv_bfloat162(h0, h1);
        *(__nv_bfloat162*)(g_flo + base) = __nv_bfloat162(l0, l1);
    }
}

// ---------------------------------------------------------------------------
// Pairwise tile kernel on mma.sync bf16 (split hi/lo, 3 products).
// 128x128 tile / CTA, 8 warps as 2(m) x 4(n), warp tile 64x32.
// ---------------------------------------------------------------------------
__global__ __launch_bounds__(256, 2) void pair_mma(const int* __restrict__ yl) {
    extern __shared__ __align__(128) char dyn[];
    __shared__ float sqA[BT], sqB[BT];
    __shared__ int   yA[BT],  yB[BT];
    __shared__ float red[8];

    const int tid  = threadIdx.x;
    const int wid  = tid >> 5;
    const int lane = tid & 31;
    const int warp_m = wid >> 2;      // 0..1
    const int warp_n = wid & 3;       // 0..3
    const uint32_t sb = smem_u32(dyn);

    // decode linear upper-tri tile index -> (ti, tj), tj >= ti
    int idx = blockIdx.x;
    int ti = (int)((2.f * NT + 1.f - sqrtf((2.f * NT + 1.f) * (2.f * NT + 1.f) - 8.f * (float)idx)) * 0.5f);
    while (ti > 0 && ti * NT - ti * (ti - 1) / 2 > idx) ti--;
    while ((ti + 1) * NT - (ti + 1) * ti / 2 <= idx) ti++;
    const int tj = ti + (idx - (ti * NT - ti * (ti - 1) / 2));
    const int i0 = ti * BT, j0 = tj * BT;

    // stage 4 bf16 tiles (A/B x hi/lo), row stride LDB bytes
#pragma unroll
    for (int rep = 0; rep < 16; rep++) {
        int lin  = rep * 256 + tid;          // 0..4095
        int tile = lin >> 10;                // 0..3
        int rem  = lin & 1023;
        int row  = rem >> 3;
        int ch   = rem & 7;
        int rbase = (tile & 2) ? j0 : i0;
        const __nv_bfloat16* src = ((tile & 1) ? g_flo : g_fhi) + (size_t)(rbase + row) * NK;
        uint4 v = *((const uint4*)src + ch);
        *(uint4*)(dyn + tile * TILE_BYTES + row * LDB + ch * 16) = v;
    }
    if (tid < BT) { sqA[tid] = g_sq[i0 + tid]; yA[tid] = yl[i0 + tid]; }
    else          { int t = tid - BT; sqB[t] = g_sq[j0 + t]; yB[t] = yl[j0 + t]; }
    __syncthreads();

    float acc[4][4][4];   // [mi][ni][frag]
#pragma unroll
    for (int mi = 0; mi < 4; mi++)
#pragma unroll
        for (int ni = 0; ni < 4; ni++)
#pragma unroll
            for (int r = 0; r < 4; r++) acc[mi][ni][r] = 0.f;

    // per-thread ldmatrix addresses
    const uint32_t a_base = sb + (uint32_t)((warp_m * 64 + (lane & 15)) * LDB + (lane >> 4) * 16);
    const uint32_t b_base = sb + (uint32_t)((warp_n * 32 + (lane & 7)) * LDB + ((lane >> 3) & 1) * 16);

    // 3 product passes: (A_hi,B_hi), (A_hi,B_lo), (A_lo,B_hi)
#pragma unroll
    for (int pass = 0; pass < 3; pass++) {
        const uint32_t aoff = (pass == 2) ? SM_A_LO : SM_A_HI;
        const uint32_t boff = (pass == 1) ? SM_B_LO : SM_B_HI;
#pragma unroll
        for (int ks = 0; ks < 4; ks++) {
            uint32_t afr[4][4];
            uint32_t bfr[4][2];
#pragma unroll
            for (int mi = 0; mi < 4; mi++)
                ldsm_x4(afr[mi], a_base + aoff + (uint32_t)(mi * 16 * LDB + ks * 32));
#pragma unroll
            for (int ni = 0; ni < 4; ni++)
                ldsm_x2(bfr[ni], b_base + boff + (uint32_t)(ni * 8 * LDB + ks * 32));
#pragma unroll
            for (int mi = 0; mi < 4; mi++)
#pragma unroll
                for (int ni = 0; ni < 4; ni++)
                    mma_bf16(acc[mi][ni], afr[mi], bfr[ni]);
        }
    }

    // epilogue: D -> hinge -> sum
    float local = 0.f;
#pragma unroll
    for (int mi = 0; mi < 4; mi++) {
        int r0 = warp_m * 64 + mi * 16 + (lane >> 2);
        float s0 = sqA[r0],     s1v = sqA[r0 + 8];
        int   y0 = yA[r0],      y1v = yA[r0 + 8];
#pragma unroll
        for (int ni = 0; ni < 4; ni++) {
            int c0 = warp_n * 32 + ni * 8 + (lane & 3) * 2;
#pragma unroll
            for (int h = 0; h < 2; h++) {           // col pair
                int col = c0 + h;
                float sB = sqB[col];
                int   yB_ = yB[col];
                float D0 = fmaf(-2.f, acc[mi][ni][h], s0 + sB);
                D0 = fmaxf(D0, 0.f);
                local += (y0 == yB_) ? D0 : fmaxf(32.f - D0, 0.f);
                float D1 = fmaf(-2.f, acc[mi][ni][2 + h], s1v + sB);
                D1 = fmaxf(D1, 0.f);
                local += (y1v == yB_) ? D1 : fmaxf(32.f - D1, 0.f);
            }
        }
    }
    if (ti != tj) local *= 2.f;

    local = warp_sum(local);
    if (lane == 0) red[wid] = local;
    __syncthreads();
    if (tid == 0) {
        float t = 0.f;
#pragma unroll
        for (int i = 0; i < 8; i++) t += red[i];
        g_pair_partial[blockIdx.x] = t;
    }
}

// ---------------------------------------------------------------------------
// Deterministic final reduction + combine
// ---------------------------------------------------------------------------
__global__ void finalize_kernel(float* __restrict__ out) {
    __shared__ double red[16];
    int tid = threadIdx.x;
    float sp = 0.f, s1 = 0.f, s2 = 0.f, sq = 0.f;
    for (int i = tid; i < NPAIR; i += 512) sp += g_pair_partial[i];
    for (int i = tid; i < NB / 8; i += 512) {
        s1 += g_ce_yi[i]; s2 += g_ce_ym[i]; sq += g_qua[i];
    }
    double d = (double)sp * (1.0 / (4.0 * (double)NB * (double)(NB - 1)))
             + ((double)s1 + (double)s2) * (1.0 / (double)NB)
             + (double)sq * (0.1 / ((double)NB * (double)NK));
    d = warp_sum_d(d);
    if ((tid & 31) == 0) red[tid >> 5] = d;
    __syncthreads();
    if (tid == 0) {
        double t = 0.0;
#pragma unroll
        for (int i = 0; i < 16; i++) t += red[i];
        out[0] = (float)t;
    }
}

extern "C" void kernel_launch(void* const* d_in, const int* in_sizes, int n_in,
                              void* d_out, int out_size) {
    (void)in_sizes; (void)n_in; (void)out_size;
    const float* Ym = (const float*)d_in[0];
    const float* Fi = (const float*)d_in[1];
    const float* Yi = (const float*)d_in[2];
    const int*   y  = (const int*)d_in[3];
    float* out = (float*)d_out;

    cudaFuncSetAttribute(pair_mma, cudaFuncAttributeMaxDynamicSharedMemorySize, SM_DYN);

    prep_kernel<<<3 * (NB / 8), 256>>>(Fi, Yi, Ym, y);
    pair_mma<<<NPAIR, 256, SM_DYN>>>(y);
    finalize_kernel<<<1, 512>>>(out);
}